// round 10
// baseline (speedup 1.0000x reference)
#include <cuda_runtime.h>

#define NV   2000000
#define NC   2000
#define NE   16000
#define NREP 16        // replicas per cluster, padded to 32B stride

// Scratch (no cudaMalloc allowed).
// Replica r of cluster c at float4 index c*32 + r*2 (32B apart: own L2 sector).
__device__ float4       g_rsum[NC * NREP * 2];
__device__ unsigned int g_icnt[NC];

__device__ __forceinline__ void red_v4(float4* a, float x, float y, float z, float w) {
    asm volatile("red.global.add.v4.f32 [%0], {%1,%2,%3,%4};"
                 :: "l"(a), "f"(x), "f"(y), "f"(z), "f"(w) : "memory");
}
__device__ __forceinline__ void red_u32(unsigned int* a, unsigned int v) {
    asm volatile("red.global.add.u32 [%0], %1;" :: "l"(a), "r"(v) : "memory");
}
__device__ __forceinline__ void unpack2(unsigned long long v, float& a, float& b) {
    asm("mov.b64 {%0, %1}, %2;" : "=f"(a), "=f"(b) : "l"(v));
}
__device__ __forceinline__ void ffma2(unsigned long long& d,
                                      unsigned long long a, unsigned long long b) {
    asm("fma.rn.f32x2 %0, %1, %2, %0;" : "+l"(d) : "l"(a), "l"(b));
}

// ---------------------------------------------------------------------------
// Kernel 1: segment sum. 148 blocks x 1024 threads: 32 warps/SM of in-flight
// LDG/RED, while per-block histogram zero+flush cost is halved vs 296 blocks.
// ---------------------------------------------------------------------------
__global__ __launch_bounds__(1024) void k_seg(const float* __restrict__ data,
                                              const int*   __restrict__ cid) {
    __shared__ unsigned int s_cnt[NC];   // 8 KB
    for (int i = threadIdx.x; i < NC; i += 1024) s_cnt[i] = 0u;
    __syncthreads();

    const int rep2 = ((blockIdx.x * 32 + (threadIdx.x >> 5)) & (NREP - 1)) * 2;
    const int NG = NV / 4;
    const int stride = gridDim.x * 1024;
#pragma unroll 2
    for (int g = blockIdx.x * 1024 + threadIdx.x; g < NG; g += stride) {
        const float4* p = (const float4*)data + (size_t)g * 5;
        float4 q0 = __ldg(p + 0);
        float4 q1 = __ldg(p + 1);
        float4 q2 = __ldg(p + 2);
        float4 q3 = __ldg(p + 3);
        float4 q4 = __ldg(p + 4);
        int4 c = __ldg((const int4*)cid + g);

        // voxel layout: [d f0 f1 f2 f3] x4 -> features are cols 1..4
        red_v4(&g_rsum[c.x * (NREP * 2) + rep2], q0.y, q0.z, q0.w, q1.x);
        red_v4(&g_rsum[c.y * (NREP * 2) + rep2], q1.z, q1.w, q2.x, q2.y);
        red_v4(&g_rsum[c.z * (NREP * 2) + rep2], q2.w, q3.x, q3.y, q3.z);
        red_v4(&g_rsum[c.w * (NREP * 2) + rep2], q4.x, q4.y, q4.z, q4.w);

        atomicAdd(&s_cnt[c.x], 1u);
        atomicAdd(&s_cnt[c.y], 1u);
        atomicAdd(&s_cnt[c.z], 1u);
        atomicAdd(&s_cnt[c.w], 1u);
    }
    __syncthreads();

    for (int i = threadIdx.x; i < NC; i += 1024) {
        unsigned int v = s_cnt[i];
        if (v) red_u32(&g_icnt[i], v);
    }
}

// ---------------------------------------------------------------------------
// Kernel 2: fused replica-reduce + gather + 2-layer MLP.
// 64 edges/block, 128 threads, grid=250, ~100KB smem (2 CTAs/SM).
// Phase B: thread tile 8 edges x 4 outs. Edge-pair FFMA2 against a
// DUPLICATED W2 ((w,w) pairs in smem): per k per thread 4x LDS.128 (64B)
// -> 16 FFMA2 = 32 FMA. 2 B/FMA, zero pack MOVs.
// ---------------------------------------------------------------------------
__global__ __launch_bounds__(128) void k_mlp(const int*   __restrict__ eidx,
                                             const float* __restrict__ W1,
                                             const float* __restrict__ b1,
                                             const float* __restrict__ W2,
                                             const float* __restrict__ b2,
                                             float*       __restrict__ out) {
    extern __shared__ float sm[];
    float* s_wdup = sm;                 // 16384 floats [128][128]: (w,w) pairs
    float* s_h    = sm + 16384;         //  8192 floats [128][64] k-major
    float* s_W1   = sm + 24576;         //  512  floats [4][128]
    float* s_b1   = s_W1 + 512;         //  128
    float* s_b2   = s_b1 + 128;         //  64
    float* s_pool = s_b2 + 64;          //  320 floats [64][5]

    const int t = threadIdx.x;

    // Build duplicated W2: s_wdup[k*128 + 2n] = s_wdup[k*128 + 2n+1] = W2[k][n]
    for (int i = t; i < 8192; i += 128) {
        int k = i >> 6, n = i & 63;
        float w = __ldg(W2 + i);
        ((float2*)(s_wdup + k * 128 + n * 2))[0] = make_float2(w, w);
    }
    if (t < 128) ((float4*)s_W1)[t] = ((const float4*)W1)[t];
    if (t < 128) s_b1[t] = b1[t];
    if (t < 64)  s_b2[t] = b2[t];

    const int base = blockIdx.x * 64;

    // Gather: 2 threads per edge; thread q sums 8 padded replicas of both
    // endpoints (16 pipelined LDG.128), 1-step shfl reduce.
    {
        int q = t & 1;
        int e = t >> 1;
        int eg = base + e;
        int a = __ldg(eidx + eg);
        int b = __ldg(eidx + NE + eg);

        const float4* ra = g_rsum + a * (NREP * 2) + q * 16;
        const float4* rb = g_rsum + b * (NREP * 2) + q * 16;
        float4 s = make_float4(0.f, 0.f, 0.f, 0.f);
#pragma unroll
        for (int r = 0; r < 8; r++) {
            float4 va = __ldg(ra + r * 2);
            float4 vb = __ldg(rb + r * 2);
            s.x += va.x + vb.x;
            s.y += va.y + vb.y;
            s.z += va.z + vb.z;
            s.w += va.w + vb.w;
        }
        s.x += __shfl_down_sync(0xffffffff, s.x, 1);
        s.y += __shfl_down_sync(0xffffffff, s.y, 1);
        s.z += __shfl_down_sync(0xffffffff, s.z, 1);
        s.w += __shfl_down_sync(0xffffffff, s.w, 1);
        if (q == 0) {
            float cnt = (float)(__ldg(g_icnt + a) + __ldg(g_icnt + b));
            float inv = 1.f / fmaxf(cnt, 1.f);
            s_pool[e * 5 + 0] = s.x * inv;
            s_pool[e * 5 + 1] = s.y * inv;
            s_pool[e * 5 + 2] = s.z * inv;
            s_pool[e * 5 + 3] = s.w * inv;
        }
    }
    __syncthreads();

    // Phase A: e = t&63, k-half kh = (t>>6)*64.
    {
        int e  = t & 63;
        int kh = (t >> 6) * 64;
        float p0 = s_pool[e * 5 + 0];
        float p1 = s_pool[e * 5 + 1];
        float p2 = s_pool[e * 5 + 2];
        float p3 = s_pool[e * 5 + 3];
#pragma unroll 4
        for (int j = 0; j < 64; j++) {
            int k = kh + j;
            float h = s_b1[k]
                    + p0 * s_W1[0 * 128 + k]
                    + p1 * s_W1[1 * 128 + k]
                    + p2 * s_W1[2 * 128 + k]
                    + p3 * s_W1[3 * 128 + k];
            s_h[k * 64 + e] = fmaxf(h, 0.f);
        }
    }
    __syncthreads();

    // Phase B: tx = out group (16 x 4 outs), ey = edge group (8 x 8 edges).
    const int tx = t & 15;
    const int ey = t >> 4;
    unsigned long long acc[4][4];   // [edge pair][out]
#pragma unroll
    for (int i = 0; i < 4; i++)
#pragma unroll
        for (int j = 0; j < 4; j++) acc[i][j] = 0ull;

    const float4* hf4 = (const float4*)s_h;       // [128][16] quads
    const float4* wf4 = (const float4*)s_wdup;    // [128][32] dup quads
#pragma unroll 4
    for (int k = 0; k < 128; k++) {
        float4 ha = hf4[k * 16 + ey * 2];         // edges e0..e3
        float4 hb = hf4[k * 16 + ey * 2 + 1];     // edges e4..e7
        float4 wa = wf4[k * 32 + tx * 2];         // (w0,w0,w1,w1)
        float4 wb = wf4[k * 32 + tx * 2 + 1];     // (w2,w2,w3,w3)
        const unsigned long long* hp0 = (const unsigned long long*)&ha;
        const unsigned long long* hp1 = (const unsigned long long*)&hb;
        const unsigned long long* wp0 = (const unsigned long long*)&wa;
        const unsigned long long* wp1 = (const unsigned long long*)&wb;
        // acc[pair][out] += (h_e, h_e') * (w_o, w_o)
        ffma2(acc[0][0], hp0[0], wp0[0]);
        ffma2(acc[0][1], hp0[0], wp0[1]);
        ffma2(acc[0][2], hp0[0], wp1[0]);
        ffma2(acc[0][3], hp0[0], wp1[1]);
        ffma2(acc[1][0], hp0[1], wp0[0]);
        ffma2(acc[1][1], hp0[1], wp0[1]);
        ffma2(acc[1][2], hp0[1], wp1[0]);
        ffma2(acc[1][3], hp0[1], wp1[1]);
        ffma2(acc[2][0], hp1[0], wp0[0]);
        ffma2(acc[2][1], hp1[0], wp0[1]);
        ffma2(acc[2][2], hp1[0], wp1[0]);
        ffma2(acc[2][3], hp1[0], wp1[1]);
        ffma2(acc[3][0], hp1[1], wp0[0]);
        ffma2(acc[3][1], hp1[1], wp0[1]);
        ffma2(acc[3][2], hp1[1], wp1[0]);
        ffma2(acc[3][3], hp1[1], wp1[1]);
    }

    float c0 = s_b2[tx * 4 + 0];
    float c1 = s_b2[tx * 4 + 1];
    float c2 = s_b2[tx * 4 + 2];
    float c3 = s_b2[tx * 4 + 3];
#pragma unroll
    for (int p = 0; p < 4; p++) {
        float a00, a01, a10, a11, a20, a21, a30, a31;
        unpack2(acc[p][0], a00, a01);   // out0 for (e, e')
        unpack2(acc[p][1], a10, a11);   // out1
        unpack2(acc[p][2], a20, a21);   // out2
        unpack2(acc[p][3], a30, a31);   // out3
        int e0 = base + ey * 8 + p * 2;
        float4 o0 = make_float4(a00 + c0, a10 + c1, a20 + c2, a30 + c3);
        float4 o1 = make_float4(a01 + c0, a11 + c1, a21 + c2, a31 + c3);
        ((float4*)out)[e0 * 16 + tx]       = o0;
        ((float4*)out)[(e0 + 1) * 16 + tx] = o1;
    }
}

// ---------------------------------------------------------------------------
// Launch: memsets -> segment sum -> fused MLP (graph-capturable)
// ---------------------------------------------------------------------------
extern "C" void kernel_launch(void* const* d_in, const int* in_sizes, int n_in,
                              void* d_out, int out_size) {
    const float* data = (const float*)d_in[0];
    const int*   cid  = (const int*)  d_in[1];
    const int*   eidx = (const int*)  d_in[2];
    const float* W1   = (const float*)d_in[3];
    const float* b1   = (const float*)d_in[4];
    const float* W2   = (const float*)d_in[5];
    const float* b2   = (const float*)d_in[6];
    float*       out  = (float*)d_out;

    cudaFuncSetAttribute(k_mlp, cudaFuncAttributeMaxDynamicSharedMemorySize, 103424);

    void *p_rsum, *p_icnt;
    cudaGetSymbolAddress(&p_rsum, g_rsum);
    cudaGetSymbolAddress(&p_icnt, g_icnt);
    cudaMemsetAsync(p_rsum, 0, NC * NREP * 2 * sizeof(float4));
    cudaMemsetAsync(p_icnt, 0, NC * sizeof(unsigned int));

    k_seg<<<148, 1024>>>(data, cid);
    k_mlp<<<NE / 64, 128, 102400>>>(eidx, W1, b1, W2, b2, out);
}

// round 11
// speedup vs baseline: 1.0942x; 1.0942x over previous
#include <cuda_runtime.h>

#define NV   2000000
#define NC   2000
#define NE   16000
#define NREP 16        // replicas per cluster, padded to 32B stride
#define GRID 296       // 2 CTAs/SM x 148 SMs: all blocks co-resident
#define TPB  256

// Scratch (no cudaMalloc allowed).
// Replica r of cluster c at float4 index c*32 + r*2 (32B apart: own L2 sector).
__device__ float4       g_rsum[NC * NREP * 2];
__device__ unsigned int g_icnt[NC];
// Monotonic grid-barrier counters (never reset; grow by GRID per launch).
__device__ unsigned int g_bar0, g_bar1;

__device__ __forceinline__ void red_v4(float4* a, float x, float y, float z, float w) {
    asm volatile("red.global.add.v4.f32 [%0], {%1,%2,%3,%4};"
                 :: "l"(a), "f"(x), "f"(y), "f"(z), "f"(w) : "memory");
}
__device__ __forceinline__ void red_u32(unsigned int* a, unsigned int v) {
    asm volatile("red.global.add.u32 [%0], %1;" :: "l"(a), "r"(v) : "memory");
}
__device__ __forceinline__ unsigned long long pack2(float a, float b) {
    unsigned long long r;
    asm("mov.b64 %0, {%1, %2};" : "=l"(r) : "f"(a), "f"(b));
    return r;
}
__device__ __forceinline__ void unpack2(unsigned long long v, float& a, float& b) {
    asm("mov.b64 {%0, %1}, %2;" : "=f"(a), "=f"(b) : "l"(v));
}
__device__ __forceinline__ void ffma2(unsigned long long& d,
                                      unsigned long long a, unsigned long long b) {
    asm("fma.rn.f32x2 %0, %1, %2, %0;" : "+l"(d) : "l"(a), "l"(b));
}

// Software grid barrier: monotonic counter, wrap-free across graph replays.
// All GRID blocks are co-resident (2 CTAs/SM), so spinning is deadlock-free.
__device__ __forceinline__ void grid_barrier(unsigned int* ctr) {
    __syncthreads();
    if (threadIdx.x == 0) {
        __threadfence();                              // release prior writes
        unsigned int t = atomicAdd(ctr, 1u);
        unsigned int target = (t / GRID + 1u) * GRID;
        unsigned int v;
        do {
            asm volatile("ld.acquire.gpu.u32 %0, [%1];" : "=r"(v) : "l"(ctr));
        } while (v < target);
        __threadfence();                              // acquire remote writes
    }
    __syncthreads();
}

// ---------------------------------------------------------------------------
// ONE fused kernel: zero -> [grid barrier] -> segment sum -> [grid barrier]
// -> edge MLP. Eliminates 3 graph nodes of fixed overhead; MLP gather hits
// warm L2. smem: W2 [0,32KB) | h [32KB,64KB) | misc (hist / W1+b+pool) 8KB.
// ---------------------------------------------------------------------------
__global__ __launch_bounds__(TPB) void k_fused(const float* __restrict__ data,
                                               const int*   __restrict__ cid,
                                               const int*   __restrict__ eidx,
                                               const float* __restrict__ W1,
                                               const float* __restrict__ b1,
                                               const float* __restrict__ W2,
                                               const float* __restrict__ b2,
                                               float*       __restrict__ out) {
    extern __shared__ float sm[];
    float* s_W2  = sm;                       // 8192 floats [128][64]
    float* s_h   = sm + 8192;                // 8192 floats [128][64] k-major
    float* s_misc = sm + 16384;              // 2048 floats (hist, then W1/b/pool)

    const int t   = threadIdx.x;
    const int bid = blockIdx.x;

    // ---- Phase 0: zero accumulators; preload W2; zero smem hist ----
    for (int i = bid * TPB + t; i < NC * NREP * 2; i += GRID * TPB)
        g_rsum[i] = make_float4(0.f, 0.f, 0.f, 0.f);
    for (int i = bid * TPB + t; i < NC; i += GRID * TPB)
        g_icnt[i] = 0u;
    for (int i = t; i < 8192 / 4; i += TPB)
        ((float4*)s_W2)[i] = ((const float4*)W2)[i];
    unsigned int* s_cnt = (unsigned int*)s_misc;   // 8KB histogram
    for (int i = t; i < NC; i += TPB) s_cnt[i] = 0u;

    grid_barrier(&g_bar0);

    // ---- Phase 1: segment sum (proven R5 config: 296x256) ----
    {
        const int rep2 = ((bid * 8 + (t >> 5)) & (NREP - 1)) * 2;
        const int NG = NV / 4;
        const int stride = GRID * TPB;
#pragma unroll 2
        for (int g = bid * TPB + t; g < NG; g += stride) {
            const float4* p = (const float4*)data + (size_t)g * 5;
            float4 q0 = __ldg(p + 0);
            float4 q1 = __ldg(p + 1);
            float4 q2 = __ldg(p + 2);
            float4 q3 = __ldg(p + 3);
            float4 q4 = __ldg(p + 4);
            int4 c = __ldg((const int4*)cid + g);

            // voxel layout: [d f0 f1 f2 f3] x4 -> features are cols 1..4
            red_v4(&g_rsum[c.x * (NREP * 2) + rep2], q0.y, q0.z, q0.w, q1.x);
            red_v4(&g_rsum[c.y * (NREP * 2) + rep2], q1.z, q1.w, q2.x, q2.y);
            red_v4(&g_rsum[c.z * (NREP * 2) + rep2], q2.w, q3.x, q3.y, q3.z);
            red_v4(&g_rsum[c.w * (NREP * 2) + rep2], q4.x, q4.y, q4.z, q4.w);

            atomicAdd(&s_cnt[c.x], 1u);
            atomicAdd(&s_cnt[c.y], 1u);
            atomicAdd(&s_cnt[c.z], 1u);
            atomicAdd(&s_cnt[c.w], 1u);
        }
        __syncthreads();
        for (int i = t; i < NC; i += TPB) {
            unsigned int v = s_cnt[i];
            if (v) red_u32(&g_icnt[i], v);
        }
    }

    grid_barrier(&g_bar1);

    // ---- Phase 2: edge MLP on blocks 0..249 (64 edges each) ----
    if (bid >= NE / 64) return;

    float* s_W1   = s_misc;          // 512 floats [4][128]  (hist is dead)
    float* s_b1   = s_misc + 512;    // 128
    float* s_b2   = s_misc + 640;    // 64
    float* s_pool = s_misc + 704;    // 320 floats [64][5]

    __syncthreads();   // everyone past barrier; reuse misc region
    if (t < 128) ((float4*)s_W1)[t] = ((const float4*)W1)[t];
    if (t < 128) s_b1[t] = b1[t];
    if (t < 64)  s_b2[t] = b2[t];

    const int base = bid * 64;

    // Gather: 4 threads/edge, each sums 4 padded replicas of both endpoints
    // (8 pipelined LDG.128 from warm L2), 2-step shfl reduce.
    {
        int q = t & 3;
        int e = t >> 2;
        int eg = base + e;
        int a = __ldg(eidx + eg);
        int b = __ldg(eidx + NE + eg);

        const float4* ra = g_rsum + a * (NREP * 2) + q * 8;
        const float4* rb = g_rsum + b * (NREP * 2) + q * 8;
        float4 s = make_float4(0.f, 0.f, 0.f, 0.f);
#pragma unroll
        for (int r = 0; r < 4; r++) {
            float4 va = __ldg(ra + r * 2);
            float4 vb = __ldg(rb + r * 2);
            s.x += va.x + vb.x;
            s.y += va.y + vb.y;
            s.z += va.z + vb.z;
            s.w += va.w + vb.w;
        }
#pragma unroll
        for (int off = 2; off > 0; off >>= 1) {
            s.x += __shfl_down_sync(0xffffffff, s.x, off);
            s.y += __shfl_down_sync(0xffffffff, s.y, off);
            s.z += __shfl_down_sync(0xffffffff, s.z, off);
            s.w += __shfl_down_sync(0xffffffff, s.w, off);
        }
        if (q == 0) {
            float cnt = (float)(__ldg(g_icnt + a) + __ldg(g_icnt + b));
            float inv = 1.f / fmaxf(cnt, 1.f);
            s_pool[e * 5 + 0] = s.x * inv;
            s_pool[e * 5 + 1] = s.y * inv;
            s_pool[e * 5 + 2] = s.z * inv;
            s_pool[e * 5 + 3] = s.w * inv;
        }
    }
    __syncthreads();

    // Phase A: e = t&63, k-group kq = (t>>6)*32.
    {
        int e  = t & 63;
        int kq = (t >> 6) * 32;
        float p0 = s_pool[e * 5 + 0];
        float p1 = s_pool[e * 5 + 1];
        float p2 = s_pool[e * 5 + 2];
        float p3 = s_pool[e * 5 + 3];
#pragma unroll 4
        for (int j = 0; j < 32; j++) {
            int k = kq + j;
            float h = s_b1[k]
                    + p0 * s_W1[0 * 128 + k]
                    + p1 * s_W1[1 * 128 + k]
                    + p2 * s_W1[2 * 128 + k]
                    + p3 * s_W1[3 * 128 + k];
            s_h[k * 64 + e] = fmaxf(h, 0.f);
        }
    }
    __syncthreads();

    // Phase B: 4 edges x 4 outs per thread, packed f32x2 accumulators.
    const int tx = t & 15;
    const int ty = t >> 4;
    unsigned long long acc[4][2];
#pragma unroll
    for (int i = 0; i < 4; i++) { acc[i][0] = 0ull; acc[i][1] = 0ull; }

    const float4* hf4 = (const float4*)s_h;    // [128][16]
    const float4* wf4 = (const float4*)s_W2;   // [128][16]
#pragma unroll 4
    for (int k = 0; k < 128; k++) {
        float4 w = wf4[k * 16 + tx];           // conflict-free
        float4 h = hf4[k * 16 + ty];           // broadcast
        unsigned long long w01 = pack2(w.x, w.y);
        unsigned long long w23 = pack2(w.z, w.w);
        float hv[4] = {h.x, h.y, h.z, h.w};
#pragma unroll
        for (int i = 0; i < 4; i++) {
            unsigned long long hh = pack2(hv[i], hv[i]);
            ffma2(acc[i][0], hh, w01);
            ffma2(acc[i][1], hh, w23);
        }
    }

    float c0 = s_b2[tx * 4 + 0];
    float c1 = s_b2[tx * 4 + 1];
    float c2 = s_b2[tx * 4 + 2];
    float c3 = s_b2[tx * 4 + 3];
#pragma unroll
    for (int i = 0; i < 4; i++) {
        int e = base + ty * 4 + i;
        float a0, a1, a2, a3;
        unpack2(acc[i][0], a0, a1);
        unpack2(acc[i][1], a2, a3);
        float4 o = make_float4(a0 + c0, a1 + c1, a2 + c2, a3 + c3);
        ((float4*)out)[e * 16 + tx] = o;
    }
}

// ---------------------------------------------------------------------------
// Launch: ONE kernel node (graph-capturable, no memsets, no extra nodes)
// ---------------------------------------------------------------------------
extern "C" void kernel_launch(void* const* d_in, const int* in_sizes, int n_in,
                              void* d_out, int out_size) {
    const float* data = (const float*)d_in[0];
    const int*   cid  = (const int*)  d_in[1];
    const int*   eidx = (const int*)  d_in[2];
    const float* W1   = (const float*)d_in[3];
    const float* b1   = (const float*)d_in[4];
    const float* W2   = (const float*)d_in[5];
    const float* b2   = (const float*)d_in[6];
    float*       out  = (float*)d_out;

    cudaFuncSetAttribute(k_fused, cudaFuncAttributeMaxDynamicSharedMemorySize, 73728);

    k_fused<<<GRID, TPB, 73728>>>(data, cid, eidx, W1, b1, W2, b2, out);
}